// round 11
// baseline (speedup 1.0000x reference)
#include <cuda_runtime.h>
#include <cuda_bf16.h>
#include <cstdint>
#include <math.h>

// Problem constants: B=4, N=1024, D=128, H=64
#define BATCH 4
#define NSEQ  1024
#define DDIM  128
#define HDIM  64
#define BN    (BATCH * NSEQ)   // 4096

typedef unsigned long long ull;

// Projections stored [row][h] row-major: cp.async 16B chunks fill smem directly.
__device__ float g_pre[BN * HDIM];   // emb @ Wa + b1
__device__ float g_hj [BN * HDIM];   // emb @ Wb

// ---------------------------------------------------------------------------
// Packed f32x2 helpers
// ---------------------------------------------------------------------------
__device__ __forceinline__ void fma2u(ull& d, ull a, ull b) {
    asm("fma.rn.f32x2 %0, %1, %2, %0;" : "+l"(d) : "l"(a), "l"(b));
}
// acc += relu(a + b) * w, fused in ONE asm region so ptxas can alias the
// f32 halves onto the b64 pair (no pack/unpack MOVs).
__device__ __forceinline__ void rfma(ull& acc, ull a, ull b, ull w) {
    asm("{\n\t.reg .f32 lo, hi;\n\t.reg .b64 s;\n\t"
        "add.rn.f32x2 s, %1, %2;\n\t"
        "mov.b64 {lo, hi}, s;\n\t"
        "max.f32 lo, lo, 0f00000000;\n\t"
        "max.f32 hi, hi, 0f00000000;\n\t"
        "mov.b64 s, {lo, hi};\n\t"
        "fma.rn.f32x2 %0, s, %3, %0;\n\t}"
        : "+l"(acc) : "l"(a), "l"(b), "l"(w));
}
__device__ __forceinline__ float lo32(ull a) {
    return __uint_as_float((unsigned int)(a & 0xffffffffull));
}
__device__ __forceinline__ float hi32(ull a) {
    return __uint_as_float((unsigned int)(a >> 32));
}
__device__ __forceinline__ float tanh_approx(float x) {
    float y;
    asm("tanh.approx.f32 %0, %1;" : "=f"(y) : "f"(x));
    return y;
}
__device__ __forceinline__ void cp16(unsigned int dst, const float* src) {
    asm volatile("cp.async.ca.shared.global [%0], [%1], 16;"
                 :: "r"(dst), "l"(src));
}

// ---------------------------------------------------------------------------
// Kernel A: projections. 32-row tiles, grid (128, 2) = 256 blocks -> all SMs.
// Warp owns 8 output cols (w-loads warp-broadcast), lane owns 1 row
// (e-loads stride 130 -> conflict-free). Stores row-major [row][64].
// dyn smem = (64*130 + 32*130) * 4 = 49920 B
// ---------------------------------------------------------------------------
__global__ __launch_bounds__(256) void precompute_kernel(
    const float* __restrict__ emb, const float* __restrict__ W1,
    const float* __restrict__ b1)
{
    extern __shared__ float sh[];
    float* w1t = sh;              // 64 cols * 130
    float* es  = sh + 64 * 130;   // 32 rows * 130
    const int t = threadIdx.x;
    const int row0 = blockIdx.x * 32;
    const int half = blockIdx.y;  // 0 = Wa, 1 = Wb

    for (int idx = t; idx < 64 * 128; idx += 256) {
        int c = idx & 63, d = idx >> 6;
        w1t[c * 130 + d] = W1[(half * 128 + d) * 64 + c];
    }
    for (int idx = t; idx < 32 * 128; idx += 256) {
        int d = idx & 127, r = idx >> 7;
        es[r * 130 + d] = emb[(row0 + r) * 128 + d];
    }
    __syncthreads();

    const int lane = t & 31;
    const int w    = t >> 5;
    const int c0   = w * 8;

    ull acc[8];
    #pragma unroll
    for (int cc = 0; cc < 8; cc++) acc[cc] = 0ull;

    const float* ep = es + lane * 130;

    #pragma unroll 4
    for (int d = 0; d < 128; d += 2) {
        ull e = *(const ull*)(ep + d);
        #pragma unroll
        for (int cc = 0; cc < 8; cc++) {
            ull wv = *(const ull*)(w1t + (c0 + cc) * 130 + d);
            fma2u(acc[cc], e, wv);
        }
    }

    float* dst = half ? g_hj : g_pre;
    const int rowg = row0 + lane;
    float s[8];
    #pragma unroll
    for (int cc = 0; cc < 8; cc++) {
        s[cc] = lo32(acc[cc]) + hi32(acc[cc]);
        if (half == 0) s[cc] += b1[c0 + cc];
    }
    *(float4*)(dst + rowg * 64 + c0)     = make_float4(s[0], s[1], s[2], s[3]);
    *(float4*)(dst + rowg * 64 + c0 + 4) = make_float4(s[4], s[5], s[6], s[7]);
}

// ---------------------------------------------------------------------------
// Kernel B: fused pairwise core + tanh + symmetrize + negate.
// Grid (136, 2): x = unordered tile pair (I <= J), y in {0,1}; each block
// processes batches y and y+2 sequentially (single wave, 272 blocks).
// The batch-2 fill is issued right after the batch-1 compute barrier and
// overlaps the batch-1 epilogue (tanh + stores + transpose).
// Row stride 68 words: LDS.128 j-loads conflict-free; i-loads broadcast.
// dyn smem = (4*64*68 + 64*65 + 64) * 4 = 86528 B  -> 2 CTAs/SM
// ---------------------------------------------------------------------------
#define TSTRIDE 68
#define ARRW    (64 * TSTRIDE)       // 4352 words per array

__global__ __launch_bounds__(256, 2) void pair_sym_kernel(
    const float* __restrict__ W2, const float* __restrict__ b2,
    float* __restrict__ out)
{
    extern __shared__ float shB[];
    float* vs  = shB + 4 * ARRW;     // 64*65 transpose buffer (separate!)
    float* w2s = vs + 64 * 65;       // 64

    const int t = threadIdx.x;

    // Decode unordered pair (I, J), I <= J
    int p = blockIdx.x;
    int I = 0;
    while (p >= 16 - I) { p -= 16 - I; I++; }
    const int J = I + p;

    // Fill: 64-thread group per array, 16 x 16B cp.async per thread.
    const int arr = t >> 6;          // 0..3
    const int sub = t & 63;
    const unsigned int sbase = (unsigned int)__cvta_generic_to_shared(shB);
    const unsigned int dbase = sbase + (unsigned int)(arr * ARRW) * 4u;

    auto fill_batch = [&](int b) {
        const int baseI = b * NSEQ + I * 64;
        const int baseJ = b * NSEQ + J * 64;
        const float* srcb =
            (arr == 0) ? g_pre + baseI * 64 :
            (arr == 1) ? g_hj  + baseI * 64 :
            (arr == 2) ? g_pre + baseJ * 64 :
                         g_hj  + baseJ * 64;
        #pragma unroll
        for (int e = 0; e < 16; e++) {
            int idx = sub + 64 * e;
            int row = idx >> 4;
            int q   = (idx & 15) * 4;
            cp16(dbase + (unsigned int)(row * TSTRIDE + q) * 4u,
                 srcb + row * 64 + q);
        }
        asm volatile("cp.async.commit_group;");
    };

    fill_batch(blockIdx.y);
    if (t < 64) w2s[t] = W2[t];

    const int tx = t & 15;
    const int ty = t >> 4;
    const float b2v = b2[0];

    const float* pAI = shB            + ty * TSTRIDE;   // preI rows
    const float* pHI = shB + ARRW     + ty * TSTRIDE;   // hjI rows
    const float* pPJ = shB + 2 * ARRW + tx * TSTRIDE;   // preJ rows
    const float* pHJ = shB + 3 * ARRW + tx * TSTRIDE;   // hjJ rows

    for (int bb = 0; bb < 2; bb++) {
        const int b = blockIdx.y + 2 * bb;

        ull acc1[4][4], acc2[4][4];
        #pragma unroll
        for (int r = 0; r < 4; r++)
            #pragma unroll
            for (int c = 0; c < 4; c++) { acc1[r][c] = 0ull; acc2[r][c] = 0ull; }

        asm volatile("cp.async.wait_group 0;");
        __syncthreads();

        #pragma unroll 2
        for (int hh = 0; hh < HDIM; hh += 4) {
            ulonglong2 wv = *(const ulonglong2*)(w2s + hh);
            ulonglong2 aI[4], bI[4];
            #pragma unroll
            for (int r = 0; r < 4; r++) {
                aI[r] = *(const ulonglong2*)(pAI + (16 * r) * TSTRIDE + hh);
                bI[r] = *(const ulonglong2*)(pHI + (16 * r) * TSTRIDE + hh);
            }
            #pragma unroll
            for (int c = 0; c < 4; c++) {
                ulonglong2 pJ = *(const ulonglong2*)(pPJ + (16 * c) * TSTRIDE + hh);
                ulonglong2 bJ = *(const ulonglong2*)(pHJ + (16 * c) * TSTRIDE + hh);
                #pragma unroll
                for (int r = 0; r < 4; r++) {
                    rfma(acc1[r][c], aI[r].x, bJ.x, wv.x);
                    rfma(acc1[r][c], aI[r].y, bJ.y, wv.y);
                    rfma(acc2[r][c], pJ.x, bI[r].x, wv.x);
                    rfma(acc2[r][c], pJ.y, bI[r].y, wv.y);
                }
            }
        }

        __syncthreads();                 // all warps done reading tiles
        if (bb == 0) fill_batch(blockIdx.y + 2);   // overlap with epilogue

        float* outB = out + (size_t)b * NSEQ * NSEQ;

        // Final values + direct (coalesced) store of out[I+i][J+j]
        float v[4][4];
        #pragma unroll
        for (int r = 0; r < 4; r++) {
            int i = ty + 16 * r;
            #pragma unroll
            for (int c = 0; c < 4; c++) {
                int j = tx + 16 * c;
                float s1 = lo32(acc1[r][c]) + hi32(acc1[r][c]) + b2v;
                float s2 = lo32(acc2[r][c]) + hi32(acc2[r][c]) + b2v;
                float vv = -0.5f * (tanh_approx(s1) + tanh_approx(s2));
                v[r][c] = vv;
                outB[(I * 64 + i) * NSEQ + (J * 64 + j)] = vv;
            }
        }

        // Mirror store out[J+j][I+i] via padded smem transpose (stride 65).
        #pragma unroll
        for (int r = 0; r < 4; r++)
            #pragma unroll
            for (int c = 0; c < 4; c++)
                vs[(ty + 16 * r) * 65 + (tx + 16 * c)] = v[r][c];
        __syncthreads();
        #pragma unroll
        for (int r = 0; r < 4; r++) {
            int jj = ty + 16 * r;
            #pragma unroll
            for (int c = 0; c < 4; c++) {
                int ii = tx + 16 * c;
                outB[(J * 64 + jj) * NSEQ + (I * 64 + ii)] = vs[ii * 65 + jj];
            }
        }
    }
}

// ---------------------------------------------------------------------------
extern "C" void kernel_launch(void* const* d_in, const int* in_sizes, int n_in,
                              void* d_out, int out_size)
{
    const float* emb = (const float*)d_in[0];
    const float* W1  = (const float*)d_in[1];
    const float* b1  = (const float*)d_in[2];
    const float* W2  = (const float*)d_in[3];
    const float* b2  = (const float*)d_in[4];
    float* out = (float*)d_out;

    const int smemA = (64 * 130 + 32 * 130) * 4;           // 49920
    const int smemB = (4 * ARRW + 64 * 65 + 64) * 4;       // 86528

    cudaFuncSetAttribute(precompute_kernel,
                         cudaFuncAttributeMaxDynamicSharedMemorySize, smemA);
    cudaFuncSetAttribute(pair_sym_kernel,
                         cudaFuncAttributeMaxDynamicSharedMemorySize, smemB);

    precompute_kernel<<<dim3(128, 2), 256, smemA>>>(emb, W1, b1);
    pair_sym_kernel<<<dim3(136, 2), 256, smemB>>>(W2, b2, out);
}